// round 6
// baseline (speedup 1.0000x reference)
#include <cuda_runtime.h>

// TpsGridGen: theta (64, 50) -> grid (64, 256, 192, 2) fp32
// Fused kernel, occupancy-tuned (6 blocks/SM, 80-reg cap):
//   Phase A: coef solve [W;A] = Li[:,:25]@(theta+P), Li via warp-uniform LDS
//            broadcast (no LDC). Coefs written to their own smem buffer
//            IMMEDIATELY so acc regs die before the U2 register peak.
//   Phase B: per-pixel RBF eval, packed fma.rn.f32x2, 2 accumulator chains.

#define OUT_H 256
#define OUT_W 192
#define NCP   25
#define NB    64
#define NCOEF 28   // 25 RBF + [1, gx, gy] affine

// Control-point coords: P_X[k] = ax[k/5], P_Y[k] = ax[k%5], ax = linspace(-1,1,5)
__host__ __device__ constexpr float cpx(int n) { return 0.5f * (float)(n / 5) - 1.0f; }
__host__ __device__ constexpr float cpy(int n) { return 0.5f * (float)(n % 5) - 1.0f; }

// ---------------------------------------------------------------------------
// Compile-time constants (constexpr fp64 Gauss-Jordan w/ pivoting + clog)
// ---------------------------------------------------------------------------
struct TPSConst {
    float li[NCOEF][NCP];
};

constexpr double cfabs(double x) { return x < 0.0 ? -x : x; }

constexpr double clog(double x) {
    int e = 0;
    while (x >= 1.4142135623730951) { x *= 0.5; e++; }
    while (x <  0.7071067811865476) { x *= 2.0; e--; }
    double t  = (x - 1.0) / (x + 1.0);
    double t2 = t * t;
    double p = t, s = 0.0;
    for (int k = 0; k < 27; k++) { s += p / (double)(2 * k + 1); p *= t2; }
    return 2.0 * s + (double)e * 0.6931471805599453094172321214581766;
}

constexpr TPSConst make_tps() {
    TPSConst r{};
    const double ax[5] = {-1.0, -0.5, 0.0, 0.5, 1.0};
    double PX[NCP] = {}, PY[NCP] = {};
    for (int i = 0; i < 5; i++)
        for (int j = 0; j < 5; j++) { PX[i * 5 + j] = ax[i]; PY[i * 5 + j] = ax[j]; }

    double a[28][56] = {};
    for (int i = 0; i < 25; i++)
        for (int j = 0; j < 25; j++) {
            if (i == j) { a[i][j] = 0.0; }
            else {
                double dx = PX[i] - PX[j], dy = PY[i] - PY[j];
                double d2 = dx * dx + dy * dy;
                a[i][j] = d2 * clog(d2);
            }
        }
    for (int i = 0; i < 25; i++) {
        a[i][25] = 1.0; a[i][26] = PX[i]; a[i][27] = PY[i];
        a[25][i] = 1.0; a[26][i] = PX[i]; a[27][i] = PY[i];
    }
    for (int i = 0; i < 28; i++) a[i][28 + i] = 1.0;

    for (int k = 0; k < 28; k++) {
        int piv = k; double best = cfabs(a[k][k]);
        for (int i = k + 1; i < 28; i++) {
            double v = cfabs(a[i][k]);
            if (v > best) { best = v; piv = i; }
        }
        if (piv != k)
            for (int j = 0; j < 56; j++) {
                double tmp = a[k][j]; a[k][j] = a[piv][j]; a[piv][j] = tmp;
            }
        double inv = 1.0 / a[k][k];
        for (int j = 0; j < 56; j++) a[k][j] *= inv;
        for (int i = 0; i < 28; i++) {
            if (i == k) continue;
            double f = a[i][k];
            if (f != 0.0)
                for (int j = 0; j < 56; j++) a[i][j] -= f * a[k][j];
        }
    }
    for (int n = 0; n < NCOEF; n++)
        for (int m = 0; m < NCP; m++)
            r.li[n][m] = (float)a[n][28 + m];
    return r;
}

// Transposed + lane-duplicated Li (staged to smem per block).
// v[m][part][j] = dup(li[part*7+j][m]); j padded to 8 -> 6400 B.
struct alignas(16) TPSLi2 { float2 v[NCP][4][8]; };

constexpr TPSLi2 make_li2() {
    TPSLi2 r{};
    TPSConst t = make_tps();
    for (int m = 0; m < NCP; m++)
        for (int part = 0; part < 4; part++)
            for (int j = 0; j < 7; j++) {
                float v = t.li[part * 7 + j][m];
                r.v[m][part][j] = float2{v, v};
            }
    return r;
}

__device__ const TPSLi2 g_li2 = make_li2();

// ---------------------------------------------------------------------------
// Packed f32x2 helpers
// ---------------------------------------------------------------------------
__device__ __forceinline__ unsigned long long pack2(float lo, float hi) {
    unsigned long long r;
    asm("mov.b64 %0, {%1, %2};" : "=l"(r) : "f"(lo), "f"(hi));
    return r;
}
__device__ __forceinline__ unsigned long long fma2(unsigned long long a,
                                                   unsigned long long b,
                                                   unsigned long long c) {
    unsigned long long d;
    asm("fma.rn.f32x2 %0, %1, %2, %3;" : "=l"(d) : "l"(a), "l"(b), "l"(c));
    return d;
}

// ---------------------------------------------------------------------------
// Fused kernel. grid (384, 2), block 128, 6 blocks/SM (80-reg cap).
// Each thread: 1 pixel x 32 batches.
// ---------------------------------------------------------------------------
__global__ __launch_bounds__(128, 6) void tps_fused_kernel(
    const float* __restrict__ theta, float2* __restrict__ out) {

    __shared__ __align__(16) float  s_theta[32 * 2 * NCP];   // 6.4 KB
    __shared__ __align__(16) float2 s_li[NCP * 4 * 8];       // 6.4 KB
    __shared__ __align__(16) float2 s_coef[32 * NCOEF];      // 7.2 KB

    const int tid   = threadIdx.x;
    const int half  = blockIdx.y;          // which 32-batch half
    const int bbase = half * 32;

    // ---- Stage theta (400 float4) + Li (400 float4) coalesced ----
    {
        const float4* tsrc = (const float4*)(theta + half * 32 * 2 * NCP);
        const float4* lsrc = (const float4*)&g_li2;
        float4* tdst = (float4*)s_theta;
        float4* ldst = (float4*)s_li;
        for (int i = tid; i < 400; i += 128) {
            tdst[i] = tsrc[i];
            ldst[i] = lsrc[i];
        }
    }
    __syncthreads();

    // ---- Phase A: coef solve + immediate writeback (acc dies early) ----
    {
        const int b    = tid & 31;         // lane -> batch
        const int part = tid >> 5;         // warp -> coef quarter (uniform)
        unsigned long long acc[7];
#pragma unroll
        for (int j = 0; j < 7; j++) acc[j] = 0ull;
        const float* trow = s_theta + b * (2 * NCP);
#pragma unroll
        for (int m = 0; m < NCP; m++) {
            const unsigned long long q2 =
                pack2(trow[m] + cpx(m), trow[NCP + m] + cpy(m));
            const unsigned long long* lrow =
                (const unsigned long long*)(s_li + (m * 4 + part) * 8);
#pragma unroll
            for (int j = 0; j < 7; j++)
                acc[j] = fma2(lrow[j], q2, acc[j]);   // LDS broadcast
        }
        unsigned long long* dst =
            (unsigned long long*)(s_coef + b * NCOEF + part * 7);
#pragma unroll
        for (int j = 0; j < 7; j++) dst[j] = acc[j];
    }

    // ---- Per-pixel RBF vector (register peak lives here, acc is dead) ----
    const int pid = blockIdx.x * 128 + tid;
    const int h = pid / OUT_W;
    const int w = pid - h * OUT_W;

    const float gx = (w == OUT_W - 1) ? 1.0f
                     : (float)(-1.0 + (double)w * (2.0 / (double)(OUT_W - 1)));
    const float gy = (h == OUT_H - 1) ? 1.0f
                     : (float)(-1.0 + (double)h * (2.0 / (double)(OUT_H - 1)));

    unsigned long long U2[NCOEF];
#pragma unroll
    for (int n = 0; n < NCP; n++) {
        const float dx = gx - cpx(n);
        const float dy = gy - cpy(n);
        const float d2 = dx * dx + dy * dy;
        const float u = (d2 == 0.0f) ? 0.0f : d2 * __logf(d2);
        U2[n] = pack2(u, u);
    }
    U2[25] = pack2(1.0f, 1.0f);
    U2[26] = pack2(gx, gx);
    U2[27] = pack2(gy, gy);

    __syncthreads();   // coefs visible

    // ---- Phase B: 32 batches, 2 accumulator chains ----
    float2* optr = out + (size_t)(bbase * OUT_H + h) * OUT_W + w;
    const size_t ostride = (size_t)OUT_H * OUT_W;
    for (int bl = 0; bl < 32; bl += 2) {
        const ulonglong2* c0 = (const ulonglong2*)(s_coef + (bl)     * NCOEF);
        const ulonglong2* c1 = (const ulonglong2*)(s_coef + (bl + 1) * NCOEF);
        unsigned long long a0 = 0ull, a1 = 0ull;
#pragma unroll
        for (int q = 0; q < NCOEF / 2; q++) {
            const ulonglong2 p0 = c0[q];
            const ulonglong2 p1 = c1[q];
            a0 = fma2(U2[2 * q],     p0.x, a0);
            a0 = fma2(U2[2 * q + 1], p0.y, a0);
            a1 = fma2(U2[2 * q],     p1.x, a1);
            a1 = fma2(U2[2 * q + 1], p1.y, a1);
        }
        float2 r0, r1;
        asm("mov.b64 {%0, %1}, %2;" : "=f"(r0.x), "=f"(r0.y) : "l"(a0));
        asm("mov.b64 {%0, %1}, %2;" : "=f"(r1.x), "=f"(r1.y) : "l"(a1));
        optr[0]       = r0;
        optr[ostride] = r1;
        optr += 2 * ostride;
    }
}

// ---------------------------------------------------------------------------
extern "C" void kernel_launch(void* const* d_in, const int* in_sizes, int n_in,
                              void* d_out, int out_size) {
    const float* theta = (const float*)d_in[0];
    (void)in_sizes; (void)n_in; (void)out_size;

    dim3 grid(OUT_H * OUT_W / 128, 2);
    tps_fused_kernel<<<grid, 128>>>(theta, (float2*)d_out);
}

// round 8
// speedup vs baseline: 1.2687x; 1.2687x over previous
#include <cuda_runtime.h>

// TpsGridGen: theta (64, 50) -> grid (64, 256, 192, 2) fp32
// Fused scalar kernel (tcgen05 unavailable: harness lowers via compute_103).
// Phase A: coef solve [W;A] = Li[:,:25]@(theta+P) via warp-uniform LDS broadcast.
// Phase B: 2 PIXELS PER THREAD. Accumulators packed (x,y) via fma.rn.f32x2,
//   U duplicated per pixel -> each coefficient LDS.128 feeds 4 FFMA2 (2 px).
//   LDS count halved vs 1-px version; stores fused to STG.128.

#define OUT_H 256
#define OUT_W 192
#define NCP   25
#define NB    64
#define NCOEF 28   // 25 RBF + [1, gx, gy] affine

// Control-point coords: P_X[k] = ax[k/5], P_Y[k] = ax[k%5], ax = linspace(-1,1,5)
__host__ __device__ constexpr float cpx(int n) { return 0.5f * (float)(n / 5) - 1.0f; }
__host__ __device__ constexpr float cpy(int n) { return 0.5f * (float)(n % 5) - 1.0f; }

// ---------------------------------------------------------------------------
// Compile-time inv(L) (constexpr fp64 Gauss-Jordan w/ pivoting + constexpr log)
// ---------------------------------------------------------------------------
struct TPSConst { float li[NCOEF][NCP]; };

constexpr double cfabs(double x) { return x < 0.0 ? -x : x; }

constexpr double clog(double x) {
    int e = 0;
    while (x >= 1.4142135623730951) { x *= 0.5; e++; }
    while (x <  0.7071067811865476) { x *= 2.0; e--; }
    double t = (x - 1.0) / (x + 1.0), t2 = t * t, p = t, s = 0.0;
    for (int k = 0; k < 27; k++) { s += p / (double)(2 * k + 1); p *= t2; }
    return 2.0 * s + (double)e * 0.6931471805599453094172321214581766;
}

constexpr TPSConst make_tps() {
    TPSConst r{};
    const double ax[5] = {-1.0, -0.5, 0.0, 0.5, 1.0};
    double PX[NCP] = {}, PY[NCP] = {};
    for (int i = 0; i < 5; i++)
        for (int j = 0; j < 5; j++) { PX[i*5+j] = ax[i]; PY[i*5+j] = ax[j]; }

    double a[28][56] = {};
    for (int i = 0; i < 25; i++)
        for (int j = 0; j < 25; j++) {
            if (i != j) {
                double dx = PX[i]-PX[j], dy = PY[i]-PY[j];
                double d2 = dx*dx + dy*dy;
                a[i][j] = d2 * clog(d2);
            }
        }
    for (int i = 0; i < 25; i++) {
        a[i][25] = 1.0; a[i][26] = PX[i]; a[i][27] = PY[i];
        a[25][i] = 1.0; a[26][i] = PX[i]; a[27][i] = PY[i];
    }
    for (int i = 0; i < 28; i++) a[i][28+i] = 1.0;

    for (int k = 0; k < 28; k++) {
        int piv = k; double best = cfabs(a[k][k]);
        for (int i = k+1; i < 28; i++) {
            double v = cfabs(a[i][k]);
            if (v > best) { best = v; piv = i; }
        }
        if (piv != k)
            for (int j = 0; j < 56; j++) {
                double t = a[k][j]; a[k][j] = a[piv][j]; a[piv][j] = t;
            }
        double inv = 1.0 / a[k][k];
        for (int j = 0; j < 56; j++) a[k][j] *= inv;
        for (int i = 0; i < 28; i++) {
            if (i == k) continue;
            double f = a[i][k];
            if (f != 0.0)
                for (int j = 0; j < 56; j++) a[i][j] -= f * a[k][j];
        }
    }
    for (int n = 0; n < NCOEF; n++)
        for (int m = 0; m < NCP; m++)
            r.li[n][m] = (float)a[n][28 + m];
    return r;
}

// Transposed + lane-duplicated Li (staged to smem per block).
struct alignas(16) TPSLi2 { float2 v[NCP][4][8]; };

constexpr TPSLi2 make_li2() {
    TPSLi2 r{};
    TPSConst t = make_tps();
    for (int m = 0; m < NCP; m++)
        for (int part = 0; part < 4; part++)
            for (int j = 0; j < 7; j++) {
                float v = t.li[part * 7 + j][m];
                r.v[m][part][j] = float2{v, v};
            }
    return r;
}

__device__ const TPSLi2 g_li2 = make_li2();

// ---------------------------------------------------------------------------
// Packed f32x2 helpers
// ---------------------------------------------------------------------------
__device__ __forceinline__ unsigned long long pack2(float lo, float hi) {
    unsigned long long r;
    asm("mov.b64 %0, {%1, %2};" : "=l"(r) : "f"(lo), "f"(hi));
    return r;
}
__device__ __forceinline__ unsigned long long fma2(unsigned long long a,
                                                   unsigned long long b,
                                                   unsigned long long c) {
    unsigned long long d;
    asm("fma.rn.f32x2 %0, %1, %2, %3;" : "=l"(d) : "l"(a), "l"(b), "l"(c));
    return d;
}

// ---------------------------------------------------------------------------
// Fused kernel. grid (192, 2), block 128, 3 blocks/SM (single wave).
// Each thread: 2 adjacent-w pixels x 32 batches.
// ---------------------------------------------------------------------------
__global__ __launch_bounds__(128, 3) void tps_fused_kernel(
    const float* __restrict__ theta, float2* __restrict__ out) {

    __shared__ __align__(16) float  s_theta[32 * 2 * NCP];   // 6.4 KB
    __shared__ __align__(16) float2 s_li[NCP * 4 * 8];       // 6.4 KB
    __shared__ __align__(16) float2 s_coef[32 * NCOEF];      // 7.2 KB

    const int tid   = threadIdx.x;
    const int half  = blockIdx.y;          // which 32-batch half
    const int bbase = half * 32;

    // ---- Stage theta (400 float4) + Li (400 float4) coalesced ----
    {
        const float4* tsrc = (const float4*)(theta + half * 32 * 2 * NCP);
        const float4* lsrc = (const float4*)&g_li2;
        float4* tdst = (float4*)s_theta;
        float4* ldst = (float4*)s_li;
        for (int i = tid; i < 400; i += 128) {
            tdst[i] = tsrc[i];
            ldst[i] = lsrc[i];
        }
    }
    __syncthreads();

    // ---- Phase A: coef solve + immediate writeback (acc dies early) ----
    {
        const int b    = tid & 31;         // lane -> batch
        const int part = tid >> 5;         // warp -> coef quarter (uniform)
        unsigned long long acc[7];
#pragma unroll
        for (int j = 0; j < 7; j++) acc[j] = 0ull;
        const float* trow = s_theta + b * (2 * NCP);
#pragma unroll
        for (int m = 0; m < NCP; m++) {
            const unsigned long long q2 =
                pack2(trow[m] + cpx(m), trow[NCP + m] + cpy(m));
            const unsigned long long* lrow =
                (const unsigned long long*)(s_li + (m * 4 + part) * 8);
#pragma unroll
            for (int j = 0; j < 7; j++)
                acc[j] = fma2(lrow[j], q2, acc[j]);   // LDS broadcast
        }
        unsigned long long* dst =
            (unsigned long long*)(s_coef + b * NCOEF + part * 7);
#pragma unroll
        for (int j = 0; j < 7; j++) dst[j] = acc[j];
    }

    // ---- Per-pixel RBF vectors for TWO adjacent-w pixels ----
    const int pid0 = blockIdx.x * 256 + tid * 2;   // even; same row as pid0+1
    const int h  = pid0 / OUT_W;
    const int w0 = pid0 - h * OUT_W;

    const float gy  = (h == OUT_H - 1) ? 1.0f
                      : (float)(-1.0 + (double)h * (2.0 / (double)(OUT_H - 1)));
    const float gx0 = (float)(-1.0 + (double)w0 * (2.0 / (double)(OUT_W - 1)));
    const float gx1 = (w0 + 1 == OUT_W - 1) ? 1.0f
                      : (float)(-1.0 + (double)(w0 + 1) * (2.0 / (double)(OUT_W - 1)));

    unsigned long long U0[NCOEF], U1[NCOEF];
#pragma unroll
    for (int n = 0; n < NCP; n++) {
        const float dy  = gy - cpy(n);
        const float dy2 = dy * dy;
        const float dx0 = gx0 - cpx(n);
        const float dx1 = gx1 - cpx(n);
        const float d20 = dx0 * dx0 + dy2;
        const float d21 = dx1 * dx1 + dy2;
        const float u0 = (d20 == 0.0f) ? 0.0f : d20 * __logf(d20);
        const float u1 = (d21 == 0.0f) ? 0.0f : d21 * __logf(d21);
        U0[n] = pack2(u0, u0);
        U1[n] = pack2(u1, u1);
    }
    U0[25] = pack2(1.0f, 1.0f);  U1[25] = U0[25];
    U0[26] = pack2(gx0, gx0);    U1[26] = pack2(gx1, gx1);
    U0[27] = pack2(gy, gy);      U1[27] = U0[27];

    __syncthreads();   // coefs visible

    // ---- Phase B: 32 batches, 2 at a time (4 chains), 2 px per coef load ----
    char* obase = (char*)out + ((size_t)(bbase * OUT_H + h) * OUT_W + w0) * 8;
    const size_t ostride = (size_t)OUT_H * OUT_W * 8;
    for (int bl = 0; bl < 32; bl += 2) {
        const ulonglong2* c0 = (const ulonglong2*)(s_coef + (bl)     * NCOEF);
        const ulonglong2* c1 = (const ulonglong2*)(s_coef + (bl + 1) * NCOEF);
        unsigned long long a00 = 0ull, a10 = 0ull, a01 = 0ull, a11 = 0ull;
#pragma unroll
        for (int q = 0; q < NCOEF / 2; q++) {
            const ulonglong2 p0 = c0[q];   // batch bl:   coef pairs 2q, 2q+1
            const ulonglong2 p1 = c1[q];   // batch bl+1
            a00 = fma2(U0[2*q],   p0.x, a00);
            a00 = fma2(U0[2*q+1], p0.y, a00);
            a10 = fma2(U1[2*q],   p0.x, a10);
            a10 = fma2(U1[2*q+1], p0.y, a10);
            a01 = fma2(U0[2*q],   p1.x, a01);
            a01 = fma2(U0[2*q+1], p1.y, a01);
            a11 = fma2(U1[2*q],   p1.x, a11);
            a11 = fma2(U1[2*q+1], p1.y, a11);
        }
        // (x,y) for px0 and px1 are 16B contiguous -> one STG.128 per batch
        ulonglong2 s0; s0.x = a00; s0.y = a10;
        ulonglong2 s1; s1.x = a01; s1.y = a11;
        *(ulonglong2*)(obase)           = s0;
        *(ulonglong2*)(obase + ostride) = s1;
        obase += 2 * ostride;
    }
}

// ---------------------------------------------------------------------------
extern "C" void kernel_launch(void* const* d_in, const int* in_sizes, int n_in,
                              void* d_out, int out_size) {
    const float* theta = (const float*)d_in[0];
    (void)in_sizes; (void)n_in; (void)out_size;

    dim3 grid(OUT_H * OUT_W / 256, 2);
    tps_fused_kernel<<<grid, 128>>>(theta, (float2*)d_out);
}